// round 6
// baseline (speedup 1.0000x reference)
#include <cuda_runtime.h>
#include <cuda_fp16.h>
#include <stdint.h>
#include <float.h>

// Problem constants
#define D      256
#define KCODES 4096
#define NROWS  16384

#define THREADS 512
#define BM 128
#define BN 256
#define STAGES_PER_TILE 16        // 2 terms x 8 chunks of k32
#define NT (KCODES / BN)          // 16
#define TOTAL_STAGES (STAGES_PER_TILE * NT)  // 256

// smem stage geometry: rows of 32 halves = 64B, no padding
#define A_STAGE_BYTES (BM * 64)   // 8192
#define B_STAGE_BYTES (BN * 64)   // 16384
#define STAGE_BYTES   (A_STAGE_BYTES + B_STAGE_BYTES)
#define SMEM_TOTAL    (2 * STAGE_BYTES)   // 49152

#define EMA_DECAY 0.99f
#define ONE_MINUS_DECAY 0.01f
#define EPS 1e-5f
#define GAP_T 0.02f               // flag threshold (~8 sigma of dropped-term error)

// ---------------- device scratch ----------------
__device__ float g_cnorm[KCODES];
__device__ float g_n[KCODES];
__device__ int   g_idx[NROWS];
__device__ int   g_flag[NROWS];
__device__ float g_scal[2];
// z: hi-only halves, k-permuted (128 half2 words per row)
__device__ __half2 g_za[(size_t)NROWS * 128];
// cb: [hi(128w) | lo(128w)] per row, k-permuted
__device__ __half2 g_cbp[(size_t)KCODES * 256];

// ---------------- helpers ----------------
__device__ __forceinline__ uint32_t smem_u32(const void* p) {
    uint32_t a;
    asm("{ .reg .u64 t; cvta.to.shared.u64 t, %1; cvt.u32.u64 %0, t; }" : "=r"(a) : "l"(p));
    return a;
}
__device__ __forceinline__ void cpasync16(uint32_t dst, const void* src) {
    asm volatile("cp.async.cg.shared.global [%0], [%1], 16;" :: "r"(dst), "l"(src));
}
__device__ __forceinline__ void cp_commit() {
    asm volatile("cp.async.commit_group;" ::: "memory");
}
__device__ __forceinline__ void cp_wait1() {
    asm volatile("cp.async.wait_group 1;" ::: "memory");
}
__device__ __forceinline__ void cp_wait0() {
    asm volatile("cp.async.wait_group 0;" ::: "memory");
}
__device__ __forceinline__ void mma_f16(float* c, uint32_t a0, uint32_t a1,
                                        uint32_t a2, uint32_t a3,
                                        uint32_t b0, uint32_t b1) {
    asm volatile(
        "mma.sync.aligned.m16n8k16.row.col.f32.f16.f16.f32 "
        "{%0,%1,%2,%3}, {%4,%5,%6,%7}, {%8,%9}, {%0,%1,%2,%3};"
        : "+f"(c[0]), "+f"(c[1]), "+f"(c[2]), "+f"(c[3])
        : "r"(a0), "r"(a1), "r"(a2), "r"(a3), "r"(b0), "r"(b1));
}

// ---------------- kernel 0: init ----------------
__global__ __launch_bounds__(256) void vq_init_kernel(
    const float* __restrict__ ema_weight, float* __restrict__ out_weight)
{
    int i = blockIdx.x * 256 + threadIdx.x;
    out_weight[i] = EMA_DECAY * ema_weight[i];
    if (i < KCODES) g_n[i] = 0.0f;
    if (i < NROWS) g_flag[i] = 0;
    if (i < 2) g_scal[i] = 0.0f;
}

// ---------------- kernel 1: codebook half-norms ----------------
__global__ __launch_bounds__(256) void vq_cnorm_kernel(const float* __restrict__ cb)
{
    int k = blockIdx.x;
    float v = cb[(size_t)k * D + threadIdx.x];
    float s = v * v;
    #pragma unroll
    for (int off = 16; off > 0; off >>= 1)
        s += __shfl_down_sync(0xffffffffu, s, off);
    __shared__ float ws[8];
    int lane = threadIdx.x & 31, wid = threadIdx.x >> 5;
    if (lane == 0) ws[wid] = s;
    __syncthreads();
    if (threadIdx.x == 0) {
        float t = 0.f;
        #pragma unroll
        for (int w = 0; w < 8; ++w) t += ws[w];
        g_cnorm[k] = 0.5f * t;
    }
}

// k-permutation shared by both pack kernels:
// within a 32-half chunk, word slot ws16 (0..15) covers dims d, d+1 where
// p0 = ws16*2; q=p0>>3; j=p0&7; kl = 2q + ((j>>1)<<3) + (j&1); d = chunk*32 + kl
__device__ __forceinline__ int perm_d(int chunk, int ws16) {
    int p0 = ws16 * 2;
    int q = p0 >> 3, j = p0 & 7;
    int kl = 2 * q + ((j >> 1) << 3) + (j & 1);
    return chunk * 32 + kl;
}

// ---------------- kernel 2a: z pack (hi only) ----------------
__global__ __launch_bounds__(256) void vq_pack_z_kernel(const float* __restrict__ src)
{
    int w   = blockIdx.x * 256 + threadIdx.x;     // word index into [NROWS][128]
    int row = w >> 7;
    int wi  = w & 127;
    int d   = perm_d(wi >> 4, wi & 15);
    float x0 = src[(size_t)row * D + d];
    float x1 = src[(size_t)row * D + d + 1];
    g_za[w] = __halves2half2(__float2half_rn(x0), __float2half_rn(x1));
}

// ---------------- kernel 2b: cb pack (hi | lo) ----------------
__global__ __launch_bounds__(256) void vq_pack_cb_kernel(const float* __restrict__ src)
{
    int w   = blockIdx.x * 256 + threadIdx.x;     // word index into [KCODES][256]
    int row = w >> 8;
    int wi  = w & 255;
    int section = wi >> 7;
    int ws  = wi & 127;
    int d   = perm_d(ws >> 4, ws & 15);
    float x0 = src[(size_t)row * D + d];
    float x1 = src[(size_t)row * D + d + 1];
    __half h0 = __float2half_rn(x0);
    __half h1 = __float2half_rn(x1);
    if (section) {
        h0 = __float2half_rn(x0 - __half2float(h0));
        h1 = __float2half_rn(x1 - __half2float(h1));
    }
    g_cbp[w] = __halves2half2(h0, h1);
}

// ---------------- kernel 3: fp16 2-term GEMM + fused top-2 argmax ----------------
__global__ __launch_bounds__(THREADS, 1) void vq_mma_kernel()
{
    extern __shared__ char smem[];
    const uint32_t sbase = smem_u32(smem);
    const int tid  = threadIdx.x;
    const int wid  = tid >> 5;
    const int lane = tid & 31;
    const int r    = lane >> 2;
    const int q    = lane & 3;
    const int wm   = (wid >> 2) * 32;
    const int wn   = (wid & 3) * 64;
    const int mBase = blockIdx.x * BM;

    uint32_t aoff[2][2];
    #pragma unroll
    for (int mf = 0; mf < 2; ++mf)
        #pragma unroll
        for (int rr = 0; rr < 2; ++rr)
            aoff[mf][rr] = (uint32_t)(wm + mf * 16 + rr * 8 + r) * 64u + (uint32_t)q * 16u;
    uint32_t boff[8];
    #pragma unroll
    for (int nf = 0; nf < 8; ++nf)
        boff[nf] = (uint32_t)(wn + nf * 8 + r) * 64u + (uint32_t)q * 16u;

    float acc[2][8][4];
    float bestS[2][2], secS[2][2];
    int   bestI[2][2];
    #pragma unroll
    for (int mf = 0; mf < 2; ++mf)
        #pragma unroll
        for (int rr = 0; rr < 2; ++rr) {
            bestS[mf][rr] = -FLT_MAX; secS[mf][rr] = -FLT_MAX; bestI[mf][rr] = 0x7fffffff;
        }

    auto issue = [&](int s, int buf) {
        int nt = s / STAGES_PER_TILE;
        int st = s - nt * STAGES_PER_TILE;
        int term = st >> 3;                // 0: B=chi, 1: B=clo (A is zhi always)
        int kc   = st & 7;
        const __half2* Asrc = g_za  + (size_t)mBase * 128 + kc * 16;
        const __half2* Bsrc = g_cbp + (size_t)(nt * BN) * 256
                              + (term ? 128 : 0) + kc * 16;
        uint32_t abase = sbase + (uint32_t)buf * STAGE_BYTES;
        uint32_t bbase = abase + A_STAGE_BYTES;
        {
            int i = tid;                   // 512 chunks for A
            int row = i >> 2, c = i & 3;
            cpasync16(abase + (uint32_t)row * 64u + (uint32_t)c * 16u,
                      Asrc + (size_t)row * 128 + c * 4);
        }
        #pragma unroll
        for (int t = 0; t < 2; ++t) {      // 1024 chunks for B
            int i = tid + t * THREADS;
            int row = i >> 2, c = i & 3;
            cpasync16(bbase + (uint32_t)row * 64u + (uint32_t)c * 16u,
                      Bsrc + (size_t)row * 256 + c * 4);
        }
        cp_commit();
    };

    issue(0, 0);

    for (int s = 0; s < TOTAL_STAGES; ++s) {
        const int buf = s & 1;
        if (s < TOTAL_STAGES - 1) { issue(s + 1, buf ^ 1); cp_wait1(); }
        else                       { cp_wait0(); }
        __syncthreads();

        int nt = s / STAGES_PER_TILE;
        int ks = s - nt * STAGES_PER_TILE;
        if (ks == 0) {
            #pragma unroll
            for (int mf = 0; mf < 2; ++mf)
                #pragma unroll
                for (int nf = 0; nf < 8; ++nf)
                    #pragma unroll
                    for (int e = 0; e < 4; ++e) acc[mf][nf][e] = 0.0f;
        }

        uint32_t abase = sbase + (uint32_t)buf * STAGE_BYTES;
        uint32_t bbase = abase + A_STAGE_BYTES;

        uint4 Af[2][2];
        #pragma unroll
        for (int mf = 0; mf < 2; ++mf)
            #pragma unroll
            for (int rr = 0; rr < 2; ++rr) {
                uint32_t addr = abase + aoff[mf][rr];
                asm volatile("ld.shared.v4.b32 {%0,%1,%2,%3}, [%4];"
                    : "=r"(Af[mf][rr].x), "=r"(Af[mf][rr].y),
                      "=r"(Af[mf][rr].z), "=r"(Af[mf][rr].w)
                    : "r"(addr));
            }
        #pragma unroll
        for (int nf = 0; nf < 8; ++nf) {
            uint4 Bf;
            uint32_t addr = bbase + boff[nf];
            asm volatile("ld.shared.v4.b32 {%0,%1,%2,%3}, [%4];"
                : "=r"(Bf.x), "=r"(Bf.y), "=r"(Bf.z), "=r"(Bf.w)
                : "r"(addr));
            #pragma unroll
            for (int mf = 0; mf < 2; ++mf) {
                mma_f16(acc[mf][nf],
                        Af[mf][0].x, Af[mf][1].x, Af[mf][0].y, Af[mf][1].y,
                        Bf.x, Bf.y);
                mma_f16(acc[mf][nf],
                        Af[mf][0].z, Af[mf][1].z, Af[mf][0].w, Af[mf][1].w,
                        Bf.z, Bf.w);
            }
        }

        if (ks == STAGES_PER_TILE - 1) {
            int ntBase = nt * BN;
            #pragma unroll
            for (int nf = 0; nf < 8; ++nf) {
                int colb = ntBase + wn + nf * 8 + q * 2;
                float cn0 = __ldg(&g_cnorm[colb]);
                float cn1 = __ldg(&g_cnorm[colb + 1]);
                #pragma unroll
                for (int mf = 0; mf < 2; ++mf) {
                    float sc[4];
                    sc[0] = acc[mf][nf][0] - cn0;
                    sc[1] = acc[mf][nf][1] - cn1;
                    sc[2] = acc[mf][nf][2] - cn0;
                    sc[3] = acc[mf][nf][3] - cn1;
                    #pragma unroll
                    for (int e = 0; e < 4; ++e) {
                        int rr = e >> 1;
                        int kk = colb + (e & 1);
                        float v = sc[e];
                        if (v > bestS[mf][rr]) {
                            secS[mf][rr] = bestS[mf][rr];
                            bestS[mf][rr] = v; bestI[mf][rr] = kk;
                        } else if (v > secS[mf][rr]) {
                            secS[mf][rr] = v;
                        }
                    }
                }
            }
        }
        __syncthreads();
    }

    // ---- final cross-thread reduction (16 candidates per row) ----
    float* redS  = reinterpret_cast<float*>(smem);
    int*   redI  = reinterpret_cast<int*>(smem + BM * 16 * 4);
    float* redS2 = reinterpret_cast<float*>(smem + BM * 16 * 8);
    int c16 = (wid & 3) * 4 + q;
    #pragma unroll
    for (int mf = 0; mf < 2; ++mf)
        #pragma unroll
        for (int rr = 0; rr < 2; ++rr) {
            int row = wm + mf * 16 + rr * 8 + r;
            redS [row * 16 + c16] = bestS[mf][rr];
            redI [row * 16 + c16] = bestI[mf][rr];
            redS2[row * 16 + c16] = secS[mf][rr];
        }
    __syncthreads();
    if (tid < BM) {
        float bs = redS[tid * 16];
        int   bi = redI[tid * 16];
        float ss = redS2[tid * 16];
        #pragma unroll
        for (int j = 1; j < 16; ++j) {
            float sv  = redS [tid * 16 + j];
            int   iv  = redI [tid * 16 + j];
            float s2v = redS2[tid * 16 + j];
            if (sv > bs || (sv == bs && iv < bi)) {
                ss = fmaxf(bs, s2v);
                bs = sv; bi = iv;
            } else {
                ss = fmaxf(ss, sv);
            }
        }
        g_idx[mBase + tid]  = bi;
        g_flag[mBase + tid] = (bs - ss < GAP_T) ? 1 : 0;
    }
}

// ---------------- kernel 3b: exact fp32 rescan for flagged rows ----------------
__global__ __launch_bounds__(256) void vq_rescan_kernel(
    const float* __restrict__ z, const float* __restrict__ cb)
{
    int gw   = (blockIdx.x * 256 + threadIdx.x) >> 5;   // global warp == row
    int lane = threadIdx.x & 31;
    if (!g_flag[gw]) return;

    float zr[8];
    #pragma unroll
    for (int j = 0; j < 8; ++j)
        zr[j] = z[(size_t)gw * D + lane + 32 * j];

    float best = -FLT_MAX;
    int   bi   = 0;
    for (int k0 = 0; k0 < KCODES; k0 += 4) {
        float p0 = 0.f, p1 = 0.f, p2 = 0.f, p3 = 0.f;
        const float* c0 = cb + (size_t)(k0 + 0) * D + lane;
        const float* c1 = cb + (size_t)(k0 + 1) * D + lane;
        const float* c2 = cb + (size_t)(k0 + 2) * D + lane;
        const float* c3 = cb + (size_t)(k0 + 3) * D + lane;
        #pragma unroll
        for (int j = 0; j < 8; ++j) {
            p0 += zr[j] * __ldg(c0 + 32 * j);
            p1 += zr[j] * __ldg(c1 + 32 * j);
            p2 += zr[j] * __ldg(c2 + 32 * j);
            p3 += zr[j] * __ldg(c3 + 32 * j);
        }
        #pragma unroll
        for (int off = 16; off > 0; off >>= 1) {
            p0 += __shfl_xor_sync(0xffffffffu, p0, off);
            p1 += __shfl_xor_sync(0xffffffffu, p1, off);
            p2 += __shfl_xor_sync(0xffffffffu, p2, off);
            p3 += __shfl_xor_sync(0xffffffffu, p3, off);
        }
        float s0 = p0 - __ldg(&g_cnorm[k0]);
        float s1 = p1 - __ldg(&g_cnorm[k0 + 1]);
        float s2 = p2 - __ldg(&g_cnorm[k0 + 2]);
        float s3 = p3 - __ldg(&g_cnorm[k0 + 3]);
        if (s0 > best) { best = s0; bi = k0; }
        if (s1 > best) { best = s1; bi = k0 + 1; }
        if (s2 > best) { best = s2; bi = k0 + 2; }
        if (s3 > best) { best = s3; bi = k0 + 3; }
    }
    if (lane == 0) g_idx[gw] = bi;
}

// ---------------- kernel 4: gather + loss + EMA scatter ----------------
__global__ __launch_bounds__(256) void vq_gather_kernel(
    const float* __restrict__ z, const float* __restrict__ cb,
    const float* __restrict__ mask,
    float* __restrict__ out_q, float* __restrict__ out_idx,
    float* __restrict__ out_weight)
{
    int tid = threadIdx.x;
    int l   = tid & 63;
    int row = blockIdx.x * 4 + (tid >> 6);
    int idx = g_idx[row];
    float m = mask[row];

    float4 zv = reinterpret_cast<const float4*>(z  + (size_t)row * D)[l];
    float4 qv = reinterpret_cast<const float4*>(cb + (size_t)idx * D)[l];
    float4 o;
    o.x = zv.x + (qv.x - zv.x); o.y = zv.y + (qv.y - zv.y);
    o.z = zv.z + (qv.z - zv.z); o.w = zv.w + (qv.w - zv.w);
    reinterpret_cast<float4*>(out_q + (size_t)row * D)[l] = o;

    if (m != 0.0f) {
        float* w = out_weight + (size_t)idx * D + l * 4;
        atomicAdd(w + 0, ONE_MINUS_DECAY * m * zv.x);
        atomicAdd(w + 1, ONE_MINUS_DECAY * m * zv.y);
        atomicAdd(w + 2, ONE_MINUS_DECAY * m * zv.z);
        atomicAdd(w + 3, ONE_MINUS_DECAY * m * zv.w);
    }

    float dx = zv.x - qv.x, dy = zv.y - qv.y, dz = zv.z - qv.z, dw = zv.w - qv.w;
    float s = m * (dx * dx + dy * dy + dz * dz + dw * dw);
    #pragma unroll
    for (int off = 16; off > 0; off >>= 1)
        s += __shfl_down_sync(0xffffffffu, s, off);
    __shared__ float ws[8];
    int lane = tid & 31, wd = tid >> 5;
    if (lane == 0) ws[wd] = s;
    __syncthreads();
    if (tid == 0) {
        float t = 0.f;
        #pragma unroll
        for (int w = 0; w < 8; ++w) t += ws[w];
        atomicAdd(&g_scal[0], t * (1.0f / (float)D));
    }
    if (l == 0) {
        out_idx[row] = (float)idx;
        atomicAdd(&g_scal[1], m);
        atomicAdd(&g_n[idx], m);
    }
}

// ---------------- kernel 5: finalize ----------------
__global__ __launch_bounds__(1024) void vq_finalize_kernel(
    const float* __restrict__ ema_count,
    float* __restrict__ out_count, float* __restrict__ out_loss)
{
    __shared__ float cbuf[KCODES];
    __shared__ float red[32];
    __shared__ float s_total;
    int tid = threadIdx.x;

    float local = 0.0f;
    for (int k = tid; k < KCODES; k += 1024) {
        float c = EMA_DECAY * ema_count[k] + ONE_MINUS_DECAY * g_n[k];
        cbuf[k] = c;
        local += c;
    }
    #pragma unroll
    for (int off = 16; off > 0; off >>= 1)
        local += __shfl_down_sync(0xffffffffu, local, off);
    int lane = tid & 31, wid = tid >> 5;
    if (lane == 0) red[wid] = local;
    __syncthreads();
    if (wid == 0) {
        float v = red[lane];
        #pragma unroll
        for (int off = 16; off > 0; off >>= 1)
            v += __shfl_down_sync(0xffffffffu, v, off);
        if (lane == 0) s_total = v;
    }
    __syncthreads();
    float total = s_total;
    float inv = total / (total + (float)KCODES * EPS);
    for (int k = tid; k < KCODES; k += 1024)
        out_count[k] = (cbuf[k] + EPS) * inv;

    if (tid == 0)
        out_loss[0] = 10.0f * 0.25f * g_scal[0] / g_scal[1];
}

// ---------------- launch ----------------
extern "C" void kernel_launch(void* const* d_in, const int* in_sizes, int n_in,
                              void* d_out, int out_size)
{
    (void)in_sizes; (void)n_in; (void)out_size;
    const float* z          = (const float*)d_in[0];
    const float* mask       = (const float*)d_in[1];
    const float* cb         = (const float*)d_in[2];
    const float* ema_count  = (const float*)d_in[3];
    const float* ema_weight = (const float*)d_in[4];

    float* out        = (float*)d_out;
    float* out_q      = out;
    float* out_idx    = out_q + (size_t)NROWS * D;
    float* out_loss   = out_idx + NROWS;
    float* out_count  = out_loss + 1;
    float* out_weight = out_count + KCODES;

    static bool attr_set = false;
    if (!attr_set) {
        cudaFuncSetAttribute(vq_mma_kernel,
                             cudaFuncAttributeMaxDynamicSharedMemorySize, SMEM_TOTAL);
        attr_set = true;
    }

    vq_init_kernel<<<(KCODES * D) / 256, 256>>>(ema_weight, out_weight);
    vq_cnorm_kernel<<<KCODES, 256>>>(cb);
    vq_pack_z_kernel<<<NROWS / 2, 256>>>(z);        // NROWS*128 half2 words
    vq_pack_cb_kernel<<<KCODES, 256>>>(cb);         // KCODES*256 half2 words
    vq_mma_kernel<<<NROWS / BM, THREADS, SMEM_TOTAL>>>();
    vq_rescan_kernel<<<NROWS * 32 / 256, 256>>>(z, cb);
    vq_gather_kernel<<<NROWS / 4, 256>>>(z, cb, mask, out_q, out_idx, out_weight);
    vq_finalize_kernel<<<1, 1024>>>(ema_count, out_count, out_loss);
}

// round 7
// speedup vs baseline: 3.1806x; 3.1806x over previous
#include <cuda_runtime.h>
#include <cuda_fp16.h>
#include <stdint.h>
#include <float.h>

// Problem constants
#define D      256
#define KCODES 4096
#define NROWS  16384

#define THREADS 512
#define BM 128
#define BN 256
#define STAGES_PER_TILE 8         // 1 term x 8 chunks of k32
#define NT (KCODES / BN)          // 16
#define TOTAL_STAGES (STAGES_PER_TILE * NT)  // 128

#define A_STAGE_BYTES (BM * 64)   // 8192
#define B_STAGE_BYTES (BN * 64)   // 16384
#define STAGE_BYTES   (A_STAGE_BYTES + B_STAGE_BYTES)
#define SMEM_TOTAL    (2 * STAGE_BYTES)   // 49152

#define EMA_DECAY 0.99f
#define ONE_MINUS_DECAY 0.01f
#define EPS 1e-5f
#define GAP_T 0.03f               // ~11 sigma of 1-term fp16 score error

// ---------------- device scratch ----------------
__device__ float g_cnorm[KCODES];
__device__ float g_n[KCODES];
__device__ int   g_idx[NROWS];
__device__ int   g_flag[NROWS];
__device__ int   g_list[NROWS];
__device__ int   g_cnt;
__device__ float g_scal[2];
// z and cb: fp16(hi) halves, k-permuted (128 half2 words per row)
__device__ __half2 g_za[(size_t)NROWS * 128];
__device__ __half2 g_cbp[(size_t)KCODES * 128];

// ---------------- helpers ----------------
__device__ __forceinline__ uint32_t smem_u32(const void* p) {
    uint32_t a;
    asm("{ .reg .u64 t; cvta.to.shared.u64 t, %1; cvt.u32.u64 %0, t; }" : "=r"(a) : "l"(p));
    return a;
}
__device__ __forceinline__ void cpasync16(uint32_t dst, const void* src) {
    asm volatile("cp.async.cg.shared.global [%0], [%1], 16;" :: "r"(dst), "l"(src));
}
__device__ __forceinline__ void cp_commit() {
    asm volatile("cp.async.commit_group;" ::: "memory");
}
__device__ __forceinline__ void cp_wait1() {
    asm volatile("cp.async.wait_group 1;" ::: "memory");
}
__device__ __forceinline__ void cp_wait0() {
    asm volatile("cp.async.wait_group 0;" ::: "memory");
}
__device__ __forceinline__ void mma_f16(float* c, uint32_t a0, uint32_t a1,
                                        uint32_t a2, uint32_t a3,
                                        uint32_t b0, uint32_t b1) {
    asm volatile(
        "mma.sync.aligned.m16n8k16.row.col.f32.f16.f16.f32 "
        "{%0,%1,%2,%3}, {%4,%5,%6,%7}, {%8,%9}, {%0,%1,%2,%3};"
        : "+f"(c[0]), "+f"(c[1]), "+f"(c[2]), "+f"(c[3])
        : "r"(a0), "r"(a1), "r"(a2), "r"(a3), "r"(b0), "r"(b1));
}

// ---------------- kernel 0: init ----------------
__global__ __launch_bounds__(256) void vq_init_kernel(
    const float* __restrict__ ema_weight, float* __restrict__ out_weight)
{
    int i = blockIdx.x * 256 + threadIdx.x;
    out_weight[i] = EMA_DECAY * ema_weight[i];
    if (i < KCODES) g_n[i] = 0.0f;
    if (i < 2) g_scal[i] = 0.0f;
    if (i == 0) g_cnt = 0;
}

// ---------------- kernel 1: codebook half-norms ----------------
__global__ __launch_bounds__(256) void vq_cnorm_kernel(const float* __restrict__ cb)
{
    int k = blockIdx.x;
    float v = cb[(size_t)k * D + threadIdx.x];
    float s = v * v;
    #pragma unroll
    for (int off = 16; off > 0; off >>= 1)
        s += __shfl_down_sync(0xffffffffu, s, off);
    __shared__ float ws[8];
    int lane = threadIdx.x & 31, wid = threadIdx.x >> 5;
    if (lane == 0) ws[wid] = s;
    __syncthreads();
    if (threadIdx.x == 0) {
        float t = 0.f;
        #pragma unroll
        for (int w = 0; w < 8; ++w) t += ws[w];
        g_cnorm[k] = 0.5f * t;
    }
}

// k-permutation: word slot ws16 (0..15) of a 32-half chunk covers dims d, d+1:
// p0 = ws16*2; q=p0>>3; j=p0&7; kl = 2q + ((j>>1)<<3) + (j&1); d = chunk*32 + kl
__device__ __forceinline__ int perm_d(int chunk, int ws16) {
    int p0 = ws16 * 2;
    int q = p0 >> 3, j = p0 & 7;
    int kl = 2 * q + ((j >> 1) << 3) + (j & 1);
    return chunk * 32 + kl;
}

// ---------------- kernel 2: fp16 pack (hi only), rows of 128 half2 words ------
__global__ __launch_bounds__(256) void vq_pack_kernel(const float* __restrict__ src, int isB)
{
    int w   = blockIdx.x * 256 + threadIdx.x;
    int row = w >> 7;
    int wi  = w & 127;
    int d   = perm_d(wi >> 4, wi & 15);
    float x0 = src[(size_t)row * D + d];
    float x1 = src[(size_t)row * D + d + 1];
    __half2 out = __halves2half2(__float2half_rn(x0), __float2half_rn(x1));
    if (isB) g_cbp[w] = out;
    else     g_za[w]  = out;
}

// ---------------- kernel 3: fp16 1-term GEMM + fused top-2 argmax ----------------
__global__ __launch_bounds__(THREADS, 1) void vq_mma_kernel()
{
    extern __shared__ char smem[];
    const uint32_t sbase = smem_u32(smem);
    const int tid  = threadIdx.x;
    const int wid  = tid >> 5;
    const int lane = tid & 31;
    const int r    = lane >> 2;
    const int q    = lane & 3;
    const int wm   = (wid >> 2) * 32;
    const int wn   = (wid & 3) * 64;
    const int mBase = blockIdx.x * BM;

    uint32_t aoff[2][2];
    #pragma unroll
    for (int mf = 0; mf < 2; ++mf)
        #pragma unroll
        for (int rr = 0; rr < 2; ++rr)
            aoff[mf][rr] = (uint32_t)(wm + mf * 16 + rr * 8 + r) * 64u + (uint32_t)q * 16u;
    uint32_t boff[8];
    #pragma unroll
    for (int nf = 0; nf < 8; ++nf)
        boff[nf] = (uint32_t)(wn + nf * 8 + r) * 64u + (uint32_t)q * 16u;

    float acc[2][8][4];
    float bestS[2][2], secS[2][2];
    int   bestI[2][2];
    #pragma unroll
    for (int mf = 0; mf < 2; ++mf)
        #pragma unroll
        for (int rr = 0; rr < 2; ++rr) {
            bestS[mf][rr] = -FLT_MAX; secS[mf][rr] = -FLT_MAX; bestI[mf][rr] = 0x7fffffff;
        }

    auto issue = [&](int s, int buf) {
        int nt = s >> 3;
        int kc = s & 7;
        const __half2* Asrc = g_za  + (size_t)mBase * 128 + kc * 16;
        const __half2* Bsrc = g_cbp + (size_t)(nt * BN) * 128 + kc * 16;
        uint32_t abase = sbase + (uint32_t)buf * STAGE_BYTES;
        uint32_t bbase = abase + A_STAGE_BYTES;
        {
            int i = tid;                   // 512 chunks for A (128 rows x 4)
            int row = i >> 2, c = i & 3;
            cpasync16(abase + (uint32_t)row * 64u + (uint32_t)c * 16u,
                      Asrc + (size_t)row * 128 + c * 4);
        }
        #pragma unroll
        for (int t = 0; t < 2; ++t) {      // 1024 chunks for B (256 rows x 4)
            int i = tid + t * THREADS;
            int row = i >> 2, c = i & 3;
            cpasync16(bbase + (uint32_t)row * 64u + (uint32_t)c * 16u,
                      Bsrc + (size_t)row * 128 + c * 4);
        }
        cp_commit();
    };

    issue(0, 0);

    for (int s = 0; s < TOTAL_STAGES; ++s) {
        const int buf = s & 1;
        if (s < TOTAL_STAGES - 1) { issue(s + 1, buf ^ 1); cp_wait1(); }
        else                       { cp_wait0(); }
        __syncthreads();

        int nt = s >> 3;
        int ks = s & 7;
        if (ks == 0) {
            #pragma unroll
            for (int mf = 0; mf < 2; ++mf)
                #pragma unroll
                for (int nf = 0; nf < 8; ++nf)
                    #pragma unroll
                    for (int e = 0; e < 4; ++e) acc[mf][nf][e] = 0.0f;
        }

        uint32_t abase = sbase + (uint32_t)buf * STAGE_BYTES;
        uint32_t bbase = abase + A_STAGE_BYTES;

        uint4 Af[2][2];
        #pragma unroll
        for (int mf = 0; mf < 2; ++mf)
            #pragma unroll
            for (int rr = 0; rr < 2; ++rr) {
                uint32_t addr = abase + aoff[mf][rr];
                asm volatile("ld.shared.v4.b32 {%0,%1,%2,%3}, [%4];"
                    : "=r"(Af[mf][rr].x), "=r"(Af[mf][rr].y),
                      "=r"(Af[mf][rr].z), "=r"(Af[mf][rr].w)
                    : "r"(addr));
            }
        #pragma unroll
        for (int nf = 0; nf < 8; ++nf) {
            uint4 Bf;
            uint32_t addr = bbase + boff[nf];
            asm volatile("ld.shared.v4.b32 {%0,%1,%2,%3}, [%4];"
                : "=r"(Bf.x), "=r"(Bf.y), "=r"(Bf.z), "=r"(Bf.w)
                : "r"(addr));
            #pragma unroll
            for (int mf = 0; mf < 2; ++mf) {
                mma_f16(acc[mf][nf],
                        Af[mf][0].x, Af[mf][1].x, Af[mf][0].y, Af[mf][1].y,
                        Bf.x, Bf.y);
                mma_f16(acc[mf][nf],
                        Af[mf][0].z, Af[mf][1].z, Af[mf][0].w, Af[mf][1].w,
                        Bf.z, Bf.w);
            }
        }

        if (ks == STAGES_PER_TILE - 1) {
            int ntBase = nt * BN;
            #pragma unroll
            for (int nf = 0; nf < 8; ++nf) {
                int colb = ntBase + wn + nf * 8 + q * 2;
                float cn0 = __ldg(&g_cnorm[colb]);
                float cn1 = __ldg(&g_cnorm[colb + 1]);
                #pragma unroll
                for (int mf = 0; mf < 2; ++mf) {
                    float sc[4];
                    sc[0] = acc[mf][nf][0] - cn0;
                    sc[1] = acc[mf][nf][1] - cn1;
                    sc[2] = acc[mf][nf][2] - cn0;
                    sc[3] = acc[mf][nf][3] - cn1;
                    #pragma unroll
                    for (int e = 0; e < 4; ++e) {
                        int rr = e >> 1;
                        int kk = colb + (e & 1);
                        float v = sc[e];
                        if (v > bestS[mf][rr]) {
                            secS[mf][rr] = bestS[mf][rr];
                            bestS[mf][rr] = v; bestI[mf][rr] = kk;
                        } else if (v > secS[mf][rr]) {
                            secS[mf][rr] = v;
                        }
                    }
                }
            }
        }
        __syncthreads();
    }

    // ---- final cross-thread reduction (16 candidates per row) ----
    float* redS  = reinterpret_cast<float*>(smem);
    int*   redI  = reinterpret_cast<int*>(smem + BM * 16 * 4);
    float* redS2 = reinterpret_cast<float*>(smem + BM * 16 * 8);
    int c16 = (wid & 3) * 4 + q;
    #pragma unroll
    for (int mf = 0; mf < 2; ++mf)
        #pragma unroll
        for (int rr = 0; rr < 2; ++rr) {
            int row = wm + mf * 16 + rr * 8 + r;
            redS [row * 16 + c16] = bestS[mf][rr];
            redI [row * 16 + c16] = bestI[mf][rr];
            redS2[row * 16 + c16] = secS[mf][rr];
        }
    __syncthreads();
    if (tid < BM) {
        float bs = redS[tid * 16];
        int   bi = redI[tid * 16];
        float ss = redS2[tid * 16];
        #pragma unroll
        for (int j = 1; j < 16; ++j) {
            float sv  = redS [tid * 16 + j];
            int   iv  = redI [tid * 16 + j];
            float s2v = redS2[tid * 16 + j];
            if (sv > bs || (sv == bs && iv < bi)) {
                ss = fmaxf(bs, s2v);
                bs = sv; bi = iv;
            } else {
                ss = fmaxf(ss, sv);
            }
        }
        g_idx[mBase + tid]  = bi;
        g_flag[mBase + tid] = (bs - ss < GAP_T) ? 1 : 0;
    }
}

// ---------------- kernel 3b: compact flags into worklist ----------------
__global__ __launch_bounds__(256) void vq_compact_kernel()
{
    int i = blockIdx.x * 256 + threadIdx.x;
    if (g_flag[i]) {
        int p = atomicAdd(&g_cnt, 1);
        g_list[p] = i;
    }
}

// ---------------- kernel 3c: exact fp32 rescan, block per flagged row --------
__global__ __launch_bounds__(256) void vq_rescan_kernel(
    const float* __restrict__ z, const float* __restrict__ cb)
{
    __shared__ float rs[8];
    __shared__ int   ri[8];
    int wid  = threadIdx.x >> 5;
    int lane = threadIdx.x & 31;
    int nf = g_cnt;

    for (int it = blockIdx.x; it < nf; it += gridDim.x) {
        int row = g_list[it];

        float zr[8];
        #pragma unroll
        for (int j = 0; j < 8; ++j)
            zr[j] = z[(size_t)row * D + lane + 32 * j];

        // warp wid handles codes [wid*512, wid*512+512)
        float best = -FLT_MAX;
        int   bi   = 0;
        int kend = wid * 512 + 512;
        for (int k0 = wid * 512; k0 < kend; k0 += 4) {
            float p0 = 0.f, p1 = 0.f, p2 = 0.f, p3 = 0.f;
            const float* c0 = cb + (size_t)(k0 + 0) * D + lane;
            const float* c1 = cb + (size_t)(k0 + 1) * D + lane;
            const float* c2 = cb + (size_t)(k0 + 2) * D + lane;
            const float* c3 = cb + (size_t)(k0 + 3) * D + lane;
            #pragma unroll
            for (int j = 0; j < 8; ++j) {
                p0 += zr[j] * __ldg(c0 + 32 * j);
                p1 += zr[j] * __ldg(c1 + 32 * j);
                p2 += zr[j] * __ldg(c2 + 32 * j);
                p3 += zr[j] * __ldg(c3 + 32 * j);
            }
            #pragma unroll
            for (int off = 16; off > 0; off >>= 1) {
                p0 += __shfl_xor_sync(0xffffffffu, p0, off);
                p1 += __shfl_xor_sync(0xffffffffu, p1, off);
                p2 += __shfl_xor_sync(0xffffffffu, p2, off);
                p3 += __shfl_xor_sync(0xffffffffu, p3, off);
            }
            float s0 = p0 - __ldg(&g_cnorm[k0]);
            float s1 = p1 - __ldg(&g_cnorm[k0 + 1]);
            float s2 = p2 - __ldg(&g_cnorm[k0 + 2]);
            float s3 = p3 - __ldg(&g_cnorm[k0 + 3]);
            if (s0 > best) { best = s0; bi = k0; }
            if (s1 > best) { best = s1; bi = k0 + 1; }
            if (s2 > best) { best = s2; bi = k0 + 2; }
            if (s3 > best) { best = s3; bi = k0 + 3; }
        }
        if (lane == 0) { rs[wid] = best; ri[wid] = bi; }
        __syncthreads();
        if (threadIdx.x == 0) {
            float bs = rs[0]; int b = ri[0];
            #pragma unroll
            for (int w = 1; w < 8; ++w) {
                if (rs[w] > bs || (rs[w] == bs && ri[w] < b)) { bs = rs[w]; b = ri[w]; }
            }
            g_idx[row] = b;
        }
        __syncthreads();
    }
}

// ---------------- kernel 4: gather + loss + EMA scatter ----------------
__global__ __launch_bounds__(256) void vq_gather_kernel(
    const float* __restrict__ z, const float* __restrict__ cb,
    const float* __restrict__ mask,
    float* __restrict__ out_q, float* __restrict__ out_idx,
    float* __restrict__ out_weight)
{
    int tid = threadIdx.x;
    int l   = tid & 63;
    int row = blockIdx.x * 4 + (tid >> 6);
    int idx = g_idx[row];
    float m = mask[row];

    float4 zv = reinterpret_cast<const float4*>(z  + (size_t)row * D)[l];
    float4 qv = reinterpret_cast<const float4*>(cb + (size_t)idx * D)[l];
    float4 o;
    o.x = zv.x + (qv.x - zv.x); o.y = zv.y + (qv.y - zv.y);
    o.z = zv.z + (qv.z - zv.z); o.w = zv.w + (qv.w - zv.w);
    reinterpret_cast<float4*>(out_q + (size_t)row * D)[l] = o;

    if (m != 0.0f) {
        float* w = out_weight + (size_t)idx * D + l * 4;
        atomicAdd(w + 0, ONE_MINUS_DECAY * m * zv.x);
        atomicAdd(w + 1, ONE_MINUS_DECAY * m * zv.y);
        atomicAdd(w + 2, ONE_MINUS_DECAY * m * zv.z);
        atomicAdd(w + 3, ONE_MINUS_DECAY * m * zv.w);
    }

    float dx = zv.x - qv.x, dy = zv.y - qv.y, dz = zv.z - qv.z, dw = zv.w - qv.w;
    float s = m * (dx * dx + dy * dy + dz * dz + dw * dw);
    #pragma unroll
    for (int off = 16; off > 0; off >>= 1)
        s += __shfl_down_sync(0xffffffffu, s, off);
    __shared__ float ws[8];
    int lane = tid & 31, wd = tid >> 5;
    if (lane == 0) ws[wd] = s;
    __syncthreads();
    if (tid == 0) {
        float t = 0.f;
        #pragma unroll
        for (int w = 0; w < 8; ++w) t += ws[w];
        atomicAdd(&g_scal[0], t * (1.0f / (float)D));
    }
    if (l == 0) {
        out_idx[row] = (float)idx;
        atomicAdd(&g_scal[1], m);
        atomicAdd(&g_n[idx], m);
    }
}

// ---------------- kernel 5: finalize ----------------
__global__ __launch_bounds__(1024) void vq_finalize_kernel(
    const float* __restrict__ ema_count,
    float* __restrict__ out_count, float* __restrict__ out_loss)
{
    __shared__ float cbuf[KCODES];
    __shared__ float red[32];
    __shared__ float s_total;
    int tid = threadIdx.x;

    float local = 0.0f;
    for (int k = tid; k < KCODES; k += 1024) {
        float c = EMA_DECAY * ema_count[k] + ONE_MINUS_DECAY * g_n[k];
        cbuf[k] = c;
        local += c;
    }
    #pragma unroll
    for (int off = 16; off > 0; off >>= 1)
        local += __shfl_down_sync(0xffffffffu, local, off);
    int lane = tid & 31, wid = tid >> 5;
    if (lane == 0) red[wid] = local;
    __syncthreads();
    if (wid == 0) {
        float v = red[lane];
        #pragma unroll
        for (int off = 16; off > 0; off >>= 1)
            v += __shfl_down_sync(0xffffffffu, v, off);
        if (lane == 0) s_total = v;
    }
    __syncthreads();
    float total = s_total;
    float inv = total / (total + (float)KCODES * EPS);
    for (int k = tid; k < KCODES; k += 1024)
        out_count[k] = (cbuf[k] + EPS) * inv;

    if (tid == 0)
        out_loss[0] = 10.0f * 0.25f * g_scal[0] / g_scal[1];
}

// ---------------- launch ----------------
extern "C" void kernel_launch(void* const* d_in, const int* in_sizes, int n_in,
                              void* d_out, int out_size)
{
    (void)in_sizes; (void)n_in; (void)out_size;
    const float* z          = (const float*)d_in[0];
    const float* mask       = (const float*)d_in[1];
    const float* cb         = (const float*)d_in[2];
    const float* ema_count  = (const float*)d_in[3];
    const float* ema_weight = (const float*)d_in[4];

    float* out        = (float*)d_out;
    float* out_q      = out;
    float* out_idx    = out_q + (size_t)NROWS * D;
    float* out_loss   = out_idx + NROWS;
    float* out_count  = out_loss + 1;
    float* out_weight = out_count + KCODES;

    static bool attr_set = false;
    if (!attr_set) {
        cudaFuncSetAttribute(vq_mma_kernel,
                             cudaFuncAttributeMaxDynamicSharedMemorySize, SMEM_TOTAL);
        attr_set = true;
    }

    vq_init_kernel<<<(KCODES * D) / 256, 256>>>(ema_weight, out_weight);
    vq_cnorm_kernel<<<KCODES, 256>>>(cb);
    vq_pack_kernel<<<NROWS / 2, 256>>>(z, 0);        // NROWS*128 half2 words
    vq_pack_kernel<<<KCODES / 2, 256>>>(cb, 1);      // KCODES*128 half2 words
    vq_mma_kernel<<<NROWS / BM, THREADS, SMEM_TOTAL>>>();
    vq_compact_kernel<<<NROWS / 256, 256>>>();
    vq_rescan_kernel<<<512, 256>>>(z, cb);
    vq_gather_kernel<<<NROWS / 4, 256>>>(z, cb, mask, out_q, out_idx, out_weight);
    vq_finalize_kernel<<<1, 1024>>>(ema_count, out_count, out_loss);
}

// round 8
// speedup vs baseline: 4.9315x; 1.5505x over previous
#include <cuda_runtime.h>
#include <cuda_fp16.h>
#include <stdint.h>
#include <float.h>

// Problem constants
#define D      256
#define KCODES 4096
#define NROWS  16384

#define THREADS 512
#define BM 128
#define BN 256
#define STAGES_PER_TILE 8         // 1 term x 8 chunks of k32
#define NT (KCODES / BN)          // 16
#define TOTAL_STAGES (STAGES_PER_TILE * NT)  // 128

#define A_STAGE_BYTES (BM * 64)   // 8192
#define B_STAGE_BYTES (BN * 64)   // 16384
#define STAGE_BYTES   (A_STAGE_BYTES + B_STAGE_BYTES)
#define SMEM_TOTAL    (2 * STAGE_BYTES)   // 49152

#define EMA_DECAY 0.99f
#define ONE_MINUS_DECAY 0.01f
#define EPS 1e-5f
#define GAP_T 0.03f               // ~5 sigma of 1-term fp16 score error

// rescan geometry
#define RG_ROWS 16                // flagged rows per block group
#define RS_ROWGRP_STRIDE 128      // row-group blocks in grid
#define RS_GRID (8 * RS_ROWGRP_STRIDE)   // 8 k-chunks x 128

// ---------------- device scratch ----------------
__device__ float g_cnorm[KCODES];
__device__ float g_n[KCODES];
__device__ int   g_idx[NROWS];
__device__ int   g_flag[NROWS];
__device__ int   g_list[NROWS];
__device__ int   g_cnt;
__device__ float g_scal[2];
__device__ unsigned long long g_best[NROWS];
__device__ float g_cbT[(size_t)D * KCODES];     // transposed codebook [d][k]
// z and cb: fp16(hi) halves, k-permuted (128 half2 words per row)
__device__ __half2 g_za[(size_t)NROWS * 128];
__device__ __half2 g_cbp[(size_t)KCODES * 128];

// ---------------- helpers ----------------
__device__ __forceinline__ uint32_t smem_u32(const void* p) {
    uint32_t a;
    asm("{ .reg .u64 t; cvta.to.shared.u64 t, %1; cvt.u32.u64 %0, t; }" : "=r"(a) : "l"(p));
    return a;
}
__device__ __forceinline__ void cpasync16(uint32_t dst, const void* src) {
    asm volatile("cp.async.cg.shared.global [%0], [%1], 16;" :: "r"(dst), "l"(src));
}
__device__ __forceinline__ void cp_commit() {
    asm volatile("cp.async.commit_group;" ::: "memory");
}
__device__ __forceinline__ void cp_wait1() {
    asm volatile("cp.async.wait_group 1;" ::: "memory");
}
__device__ __forceinline__ void cp_wait0() {
    asm volatile("cp.async.wait_group 0;" ::: "memory");
}
__device__ __forceinline__ void mma_f16(float* c, uint32_t a0, uint32_t a1,
                                        uint32_t a2, uint32_t a3,
                                        uint32_t b0, uint32_t b1) {
    asm volatile(
        "mma.sync.aligned.m16n8k16.row.col.f32.f16.f16.f32 "
        "{%0,%1,%2,%3}, {%4,%5,%6,%7}, {%8,%9}, {%0,%1,%2,%3};"
        : "+f"(c[0]), "+f"(c[1]), "+f"(c[2]), "+f"(c[3])
        : "r"(a0), "r"(a1), "r"(a2), "r"(a3), "r"(b0), "r"(b1));
}
// monotone (score, index) packing: bigger key == better score, tie -> smaller k
__device__ __forceinline__ unsigned long long pack_sk(float s, int k) {
    uint32_t b = __float_as_uint(s);
    b = (b & 0x80000000u) ? ~b : (b | 0x80000000u);
    return ((unsigned long long)b << 32) | (unsigned long long)(0xFFFFFFFFu - (uint32_t)k);
}

// ---------------- kernel 0: init ----------------
__global__ __launch_bounds__(256) void vq_init_kernel(
    const float* __restrict__ ema_weight, float* __restrict__ out_weight)
{
    int i = blockIdx.x * 256 + threadIdx.x;
    out_weight[i] = EMA_DECAY * ema_weight[i];
    if (i < KCODES) g_n[i] = 0.0f;
    if (i < NROWS) g_best[i] = 0ull;
    if (i < 2) g_scal[i] = 0.0f;
    if (i == 0) g_cnt = 0;
}

// ---------------- kernel 1: codebook half-norms ----------------
__global__ __launch_bounds__(256) void vq_cnorm_kernel(const float* __restrict__ cb)
{
    int k = blockIdx.x;
    float v = cb[(size_t)k * D + threadIdx.x];
    float s = v * v;
    #pragma unroll
    for (int off = 16; off > 0; off >>= 1)
        s += __shfl_down_sync(0xffffffffu, s, off);
    __shared__ float ws[8];
    int lane = threadIdx.x & 31, wid = threadIdx.x >> 5;
    if (lane == 0) ws[wid] = s;
    __syncthreads();
    if (threadIdx.x == 0) {
        float t = 0.f;
        #pragma unroll
        for (int w = 0; w < 8; ++w) t += ws[w];
        g_cnorm[k] = 0.5f * t;
    }
}

// ---------------- kernel 1b: codebook transpose (for rescan) ----------------
__global__ __launch_bounds__(256) void vq_transpose_kernel(const float* __restrict__ cb)
{
    __shared__ float t[32][33];
    int k0 = blockIdx.x * 32;         // code base (128 blocks)
    int d0 = blockIdx.y * 32;         // dim base (8 blocks)
    int tx = threadIdx.x & 31;
    int ty = threadIdx.x >> 5;        // 0..7
    #pragma unroll
    for (int j = 0; j < 4; ++j)
        t[ty + j * 8][tx] = cb[(size_t)(k0 + ty + j * 8) * D + d0 + tx];
    __syncthreads();
    #pragma unroll
    for (int j = 0; j < 4; ++j)
        g_cbT[(size_t)(d0 + ty + j * 8) * KCODES + k0 + tx] = t[tx][ty + j * 8];
}

// k-permutation: word slot ws16 (0..15) of a 32-half chunk covers dims d, d+1:
__device__ __forceinline__ int perm_d(int chunk, int ws16) {
    int p0 = ws16 * 2;
    int q = p0 >> 3, j = p0 & 7;
    int kl = 2 * q + ((j >> 1) << 3) + (j & 1);
    return chunk * 32 + kl;
}

// ---------------- kernel 2: fp16 pack (hi only) ----------------
__global__ __launch_bounds__(256) void vq_pack_kernel(const float* __restrict__ src, int isB)
{
    int w   = blockIdx.x * 256 + threadIdx.x;
    int row = w >> 7;
    int wi  = w & 127;
    int d   = perm_d(wi >> 4, wi & 15);
    float x0 = src[(size_t)row * D + d];
    float x1 = src[(size_t)row * D + d + 1];
    __half2 out = __halves2half2(__float2half_rn(x0), __float2half_rn(x1));
    if (isB) g_cbp[w] = out;
    else     g_za[w]  = out;
}

// ---------------- kernel 3: fp16 1-term GEMM + fused top-2 argmax ----------------
__global__ __launch_bounds__(THREADS, 1) void vq_mma_kernel()
{
    extern __shared__ char smem[];
    const uint32_t sbase = smem_u32(smem);
    const int tid  = threadIdx.x;
    const int wid  = tid >> 5;
    const int lane = tid & 31;
    const int r    = lane >> 2;
    const int q    = lane & 3;
    const int wm   = (wid >> 2) * 32;
    const int wn   = (wid & 3) * 64;
    const int mBase = blockIdx.x * BM;

    uint32_t aoff[2][2];
    #pragma unroll
    for (int mf = 0; mf < 2; ++mf)
        #pragma unroll
        for (int rr = 0; rr < 2; ++rr)
            aoff[mf][rr] = (uint32_t)(wm + mf * 16 + rr * 8 + r) * 64u + (uint32_t)q * 16u;
    uint32_t boff[8];
    #pragma unroll
    for (int nf = 0; nf < 8; ++nf)
        boff[nf] = (uint32_t)(wn + nf * 8 + r) * 64u + (uint32_t)q * 16u;

    float acc[2][8][4];
    float bestS[2][2], secS[2][2];
    int   bestI[2][2];
    #pragma unroll
    for (int mf = 0; mf < 2; ++mf)
        #pragma unroll
        for (int rr = 0; rr < 2; ++rr) {
            bestS[mf][rr] = -FLT_MAX; secS[mf][rr] = -FLT_MAX; bestI[mf][rr] = 0x7fffffff;
        }

    auto issue = [&](int s, int buf) {
        int nt = s >> 3;
        int kc = s & 7;
        const __half2* Asrc = g_za  + (size_t)mBase * 128 + kc * 16;
        const __half2* Bsrc = g_cbp + (size_t)(nt * BN) * 128 + kc * 16;
        uint32_t abase = sbase + (uint32_t)buf * STAGE_BYTES;
        uint32_t bbase = abase + A_STAGE_BYTES;
        {
            int i = tid;
            int row = i >> 2, c = i & 3;
            cpasync16(abase + (uint32_t)row * 64u + (uint32_t)c * 16u,
                      Asrc + (size_t)row * 128 + c * 4);
        }
        #pragma unroll
        for (int t = 0; t < 2; ++t) {
            int i = tid + t * THREADS;
            int row = i >> 2, c = i & 3;
            cpasync16(bbase + (uint32_t)row * 64u + (uint32_t)c * 16u,
                      Bsrc + (size_t)row * 128 + c * 4);
        }
        cp_commit();
    };

    issue(0, 0);

    for (int s = 0; s < TOTAL_STAGES; ++s) {
        const int buf = s & 1;
        if (s < TOTAL_STAGES - 1) { issue(s + 1, buf ^ 1); cp_wait1(); }
        else                       { cp_wait0(); }
        __syncthreads();

        int nt = s >> 3;
        int ks = s & 7;
        if (ks == 0) {
            #pragma unroll
            for (int mf = 0; mf < 2; ++mf)
                #pragma unroll
                for (int nf = 0; nf < 8; ++nf)
                    #pragma unroll
                    for (int e = 0; e < 4; ++e) acc[mf][nf][e] = 0.0f;
        }

        uint32_t abase = sbase + (uint32_t)buf * STAGE_BYTES;
        uint32_t bbase = abase + A_STAGE_BYTES;

        uint4 Af[2][2];
        #pragma unroll
        for (int mf = 0; mf < 2; ++mf)
            #pragma unroll
            for (int rr = 0; rr < 2; ++rr) {
                uint32_t addr = abase + aoff[mf][rr];
                asm volatile("ld.shared.v4.b32 {%0,%1,%2,%3}, [%4];"
                    : "=r"(Af[mf][rr].x), "=r"(Af[mf][rr].y),
                      "=r"(Af[mf][rr].z), "=r"(Af[mf][rr].w)
                    : "r"(addr));
            }
        #pragma unroll
        for (int nf = 0; nf < 8; ++nf) {
            uint4 Bf;
            uint32_t addr = bbase + boff[nf];
            asm volatile("ld.shared.v4.b32 {%0,%1,%2,%3}, [%4];"
                : "=r"(Bf.x), "=r"(Bf.y), "=r"(Bf.z), "=r"(Bf.w)
                : "r"(addr));
            #pragma unroll
            for (int mf = 0; mf < 2; ++mf) {
                mma_f16(acc[mf][nf],
                        Af[mf][0].x, Af[mf][1].x, Af[mf][0].y, Af[mf][1].y,
                        Bf.x, Bf.y);
                mma_f16(acc[mf][nf],
                        Af[mf][0].z, Af[mf][1].z, Af[mf][0].w, Af[mf][1].w,
                        Bf.z, Bf.w);
            }
        }

        if (ks == STAGES_PER_TILE - 1) {
            int ntBase = nt * BN;
            #pragma unroll
            for (int nf = 0; nf < 8; ++nf) {
                int colb = ntBase + wn + nf * 8 + q * 2;
                float cn0 = __ldg(&g_cnorm[colb]);
                float cn1 = __ldg(&g_cnorm[colb + 1]);
                #pragma unroll
                for (int mf = 0; mf < 2; ++mf) {
                    float sc[4];
                    sc[0] = acc[mf][nf][0] - cn0;
                    sc[1] = acc[mf][nf][1] - cn1;
                    sc[2] = acc[mf][nf][2] - cn0;
                    sc[3] = acc[mf][nf][3] - cn1;
                    #pragma unroll
                    for (int e = 0; e < 4; ++e) {
                        int rr = e >> 1;
                        int kk = colb + (e & 1);
                        float v = sc[e];
                        if (v > bestS[mf][rr]) {
                            secS[mf][rr] = bestS[mf][rr];
                            bestS[mf][rr] = v; bestI[mf][rr] = kk;
                        } else if (v > secS[mf][rr]) {
                            secS[mf][rr] = v;
                        }
                    }
                }
            }
        }
        __syncthreads();
    }

    float* redS  = reinterpret_cast<float*>(smem);
    int*   redI  = reinterpret_cast<int*>(smem + BM * 16 * 4);
    float* redS2 = reinterpret_cast<float*>(smem + BM * 16 * 8);
    int c16 = (wid & 3) * 4 + q;
    #pragma unroll
    for (int mf = 0; mf < 2; ++mf)
        #pragma unroll
        for (int rr = 0; rr < 2; ++rr) {
            int row = wm + mf * 16 + rr * 8 + r;
            redS [row * 16 + c16] = bestS[mf][rr];
            redI [row * 16 + c16] = bestI[mf][rr];
            redS2[row * 16 + c16] = secS[mf][rr];
        }
    __syncthreads();
    if (tid < BM) {
        float bs = redS[tid * 16];
        int   bi = redI[tid * 16];
        float ss = redS2[tid * 16];
        #pragma unroll
        for (int j = 1; j < 16; ++j) {
            float sv  = redS [tid * 16 + j];
            int   iv  = redI [tid * 16 + j];
            float s2v = redS2[tid * 16 + j];
            if (sv > bs || (sv == bs && iv < bi)) {
                ss = fmaxf(bs, s2v);
                bs = sv; bi = iv;
            } else {
                ss = fmaxf(ss, sv);
            }
        }
        g_idx[mBase + tid]  = bi;
        g_flag[mBase + tid] = (bs - ss < GAP_T) ? 1 : 0;
    }
}

// ---------------- kernel 3b: compact flags into worklist ----------------
__global__ __launch_bounds__(256) void vq_compact_kernel()
{
    int i = blockIdx.x * 256 + threadIdx.x;
    if (g_flag[i]) {
        int p = atomicAdd(&g_cnt, 1);
        g_list[p] = i;
    }
}

// ---------------- kernel 3c: batched exact fp32 rescan ----------------
// grid = 8 k-chunks x 128 row-group slots; 16 rows per group staged in smem;
// thread handles 2 codes; per-row (score,~k) max merged via warp shfl + atomicMax
__global__ __launch_bounds__(256) void vq_rescan_kernel(const float* __restrict__ z)
{
    __shared__ float zs[RG_ROWS][256];
    __shared__ int   rows[RG_ROWS];
    __shared__ unsigned long long wbuf[RG_ROWS][8];

    const int tid  = threadIdx.x;
    const int lane = tid & 31;
    const int wid  = tid >> 5;
    const int kc   = blockIdx.x & 7;
    const int k0   = kc * 512 + tid;          // codes k0, k0+256
    const int nf   = g_cnt;
    const int ngrp = (nf + RG_ROWS - 1) / RG_ROWS;

    const float cn0 = g_cnorm[k0];
    const float cn1 = g_cnorm[k0 + 256];

    for (int grp = blockIdx.x >> 3; grp < ngrp; grp += RS_ROWGRP_STRIDE) {
        __syncthreads();
        if (tid < RG_ROWS) {
            int i = grp * RG_ROWS + tid;
            rows[tid] = (i < nf) ? g_list[i] : -1;
        }
        __syncthreads();
        #pragma unroll 1
        for (int rr = 0; rr < RG_ROWS; ++rr) {
            int row = rows[rr];
            if (row >= 0) zs[rr][tid] = z[(size_t)row * D + tid];
        }
        __syncthreads();

        float acc0[RG_ROWS], acc1[RG_ROWS];
        #pragma unroll
        for (int rr = 0; rr < RG_ROWS; ++rr) { acc0[rr] = 0.f; acc1[rr] = 0.f; }

        #pragma unroll 2
        for (int d4 = 0; d4 < D; d4 += 4) {
            float4 c0, c1;
            const float* p = g_cbT + (size_t)d4 * KCODES + k0;
            c0.x = p[0];            c1.x = p[256];
            c0.y = p[KCODES];       c1.y = p[KCODES + 256];
            c0.z = p[2 * KCODES];   c1.z = p[2 * KCODES + 256];
            c0.w = p[3 * KCODES];   c1.w = p[3 * KCODES + 256];
            #pragma unroll
            for (int rr = 0; rr < RG_ROWS; ++rr) {
                float4 zv = *reinterpret_cast<const float4*>(&zs[rr][d4]);
                acc0[rr] += c0.x * zv.x + c0.y * zv.y + c0.z * zv.z + c0.w * zv.w;
                acc1[rr] += c1.x * zv.x + c1.y * zv.y + c1.z * zv.z + c1.w * zv.w;
            }
        }

        #pragma unroll
        for (int rr = 0; rr < RG_ROWS; ++rr) {
            unsigned long long p0 = pack_sk(acc0[rr] - cn0, k0);
            unsigned long long p1 = pack_sk(acc1[rr] - cn1, k0 + 256);
            unsigned long long pm = p0 > p1 ? p0 : p1;
            #pragma unroll
            for (int off = 16; off > 0; off >>= 1) {
                unsigned long long q = __shfl_xor_sync(0xffffffffu, pm, off);
                if (q > pm) pm = q;
            }
            if (lane == 0) wbuf[rr][wid] = pm;
        }
        __syncthreads();
        if (tid < RG_ROWS && rows[tid] >= 0) {
            unsigned long long pm = wbuf[tid][0];
            #pragma unroll
            for (int w = 1; w < 8; ++w)
                if (wbuf[tid][w] > pm) pm = wbuf[tid][w];
            atomicMax(&g_best[rows[tid]], pm);
        }
    }
}

// ---------------- kernel 3d: apply rescan results ----------------
__global__ __launch_bounds__(256) void vq_fixup_kernel()
{
    int i = blockIdx.x * 256 + threadIdx.x;
    if (g_flag[i]) {
        unsigned long long b = g_best[i];
        g_idx[i] = (int)(0xFFFFFFFFu - (uint32_t)(b & 0xFFFFFFFFull));
    }
}

// ---------------- kernel 4: gather + loss + EMA scatter ----------------
__global__ __launch_bounds__(256) void vq_gather_kernel(
    const float* __restrict__ z, const float* __restrict__ cb,
    const float* __restrict__ mask,
    float* __restrict__ out_q, float* __restrict__ out_idx,
    float* __restrict__ out_weight)
{
    int tid = threadIdx.x;
    int l   = tid & 63;
    int row = blockIdx.x * 4 + (tid >> 6);
    int idx = g_idx[row];
    float m = mask[row];

    float4 zv = reinterpret_cast<const float4*>(z  + (size_t)row * D)[l];
    float4 qv = reinterpret_cast<const float4*>(cb + (size_t)idx * D)[l];
    float4 o;
    o.x = zv.x + (qv.x - zv.x); o.y = zv.y + (qv.y - zv.y);
    o.z = zv.z + (qv.z - zv.z); o.w = zv.w + (qv.w - zv.w);
    reinterpret_cast<float4*>(out_q + (size_t)row * D)[l] = o;

    if (m != 0.0f) {
        float* w = out_weight + (size_t)idx * D + l * 4;
        atomicAdd(w + 0, ONE_MINUS_DECAY * m * zv.x);
        atomicAdd(w + 1, ONE_MINUS_DECAY * m * zv.y);
        atomicAdd(w + 2, ONE_MINUS_DECAY * m * zv.z);
        atomicAdd(w + 3, ONE_MINUS_DECAY * m * zv.w);
    }

    float dx = zv.x - qv.x, dy = zv.y - qv.y, dz = zv.z - qv.z, dw = zv.w - qv.w;
    float s = m * (dx * dx + dy * dy + dz * dz + dw * dw);
    #pragma unroll
    for (int off = 16; off > 0; off >>= 1)
        s += __shfl_down_sync(0xffffffffu, s, off);
    __shared__ float ws[8];
    int lane = tid & 31, wd = tid >> 5;
    if (lane == 0) ws[wd] = s;
    __syncthreads();
    if (tid == 0) {
        float t = 0.f;
        #pragma unroll
        for (int w = 0; w < 8; ++w) t += ws[w];
        atomicAdd(&g_scal[0], t * (1.0f / (float)D));
    }
    if (l == 0) {
        out_idx[row] = (float)idx;
        atomicAdd(&g_scal[1], m);
        atomicAdd(&g_n[idx], m);
    }
}

// ---------------- kernel 5: finalize ----------------
__global__ __launch_bounds__(1024) void vq_finalize_kernel(
    const float* __restrict__ ema_count,
    float* __restrict__ out_count, float* __restrict__ out_loss)
{
    __shared__ float cbuf[KCODES];
    __shared__ float red[32];
    __shared__ float s_total;
    int tid = threadIdx.x;

    float local = 0.0f;
    for (int k = tid; k < KCODES; k += 1024) {
        float c = EMA_DECAY * ema_count[k] + ONE_MINUS_DECAY * g_n[k];
        cbuf[k] = c;
        local += c;
    }
    #pragma unroll
    for (int off = 16; off > 0; off >>= 1)
        local += __shfl_down_sync(0xffffffffu, local, off);
    int lane = tid & 31, wid = tid >> 5;
    if (lane == 0) red[wid] = local;
    __syncthreads();
    if (wid == 0) {
        float v = red[lane];
        #pragma unroll
        for (int off = 16; off > 0; off >>= 1)
            v += __shfl_down_sync(0xffffffffu, v, off);
        if (lane == 0) s_total = v;
    }
    __syncthreads();
    float total = s_total;
    float inv = total / (total + (float)KCODES * EPS);
    for (int k = tid; k < KCODES; k += 1024)
        out_count[k] = (cbuf[k] + EPS) * inv;

    if (tid == 0)
        out_loss[0] = 10.0f * 0.25f * g_scal[0] / g_scal[1];
}

// ---------------- launch ----------------
extern "C" void kernel_launch(void* const* d_in, const int* in_sizes, int n_in,
                              void* d_out, int out_size)
{
    (void)in_sizes; (void)n_in; (void)out_size;
    const float* z          = (const float*)d_in[0];
    const float* mask       = (const float*)d_in[1];
    const float* cb         = (const float*)d_in[2];
    const float* ema_count  = (const float*)d_in[3];
    const float* ema_weight = (const float*)d_in[4];

    float* out        = (float*)d_out;
    float* out_q      = out;
    float* out_idx    = out_q + (size_t)NROWS * D;
    float* out_loss   = out_idx + NROWS;
    float* out_count  = out_loss + 1;
    float* out_weight = out_count + KCODES;

    static bool attr_set = false;
    if (!attr_set) {
        cudaFuncSetAttribute(vq_mma_kernel,
                             cudaFuncAttributeMaxDynamicSharedMemorySize, SMEM_TOTAL);
        attr_set = true;
    }

    vq_init_kernel<<<(KCODES * D) / 256, 256>>>(ema_weight, out_weight);
    vq_cnorm_kernel<<<KCODES, 256>>>(cb);
    vq_transpose_kernel<<<dim3(KCODES / 32, D / 32), 256>>>(cb);
    vq_pack_kernel<<<NROWS / 2, 256>>>(z, 0);
    vq_pack_kernel<<<KCODES / 2, 256>>>(cb, 1);
    vq_mma_kernel<<<NROWS / BM, THREADS, SMEM_TOTAL>>>();
    vq_compact_kernel<<<NROWS / 256, 256>>>();
    vq_rescan_kernel<<<RS_GRID, 256>>>(z);
    vq_fixup_kernel<<<NROWS / 256, 256>>>();
    vq_gather_kernel<<<NROWS / 4, 256>>>(z, cb, mask, out_q, out_idx, out_weight);
    vq_finalize_kernel<<<1, 1024>>>(ema_count, out_count, out_loss);
}